// round 8
// baseline (speedup 1.0000x reference)
#include <cuda_runtime.h>
#include <math.h>

#define B_ 1024
#define N_ 128
#define D_ 512

// ---- output layout (float32, concatenated in reference return order) ----
__device__ __host__ constexpr size_t KD_ = (size_t)B_ * N_ * D_;   // 67108864
__device__ __host__ constexpr size_t O1_ = KD_;                    // updated_values
__device__ __host__ constexpr size_t O2_ = 2 * KD_;                // updated_protection (B*N)
__device__ __host__ constexpr size_t O3_ = O2_ + (size_t)B_ * N_;  // write_strength (B)
__device__ __host__ constexpr size_t O4_ = O3_ + B_;               // merge_preference (B)
__device__ __host__ constexpr size_t O5_ = O4_ + B_;               // binding_strength (B)
__device__ __host__ constexpr size_t O6_ = O5_ + B_;               // overwrite.mean (B)
__device__ __host__ constexpr size_t O7_ = O6_ + B_;               // updated_protection.mean (B)
__device__ __host__ constexpr size_t O8_ = O7_ + B_;               // max_similarity (B)
__device__ __host__ constexpr size_t O9_ = O8_ + B_;               // overwrite (B*N)

// ---- scratch (__device__ globals; no allocations allowed) ----
__device__ float g_ck[B_ * D_];     // candidate_key (tanh)
__device__ float g_cv[B_ * D_];     // candidate_value (tanh)
__device__ float g_sim[B_ * N_];
__device__ float g_occ[B_ * N_];
__device__ float g_lprot[B_ * N_];
__device__ float g_ws[B_];
__device__ float g_im[B_];
__device__ float g_hmg[B_];
__device__ float g_hbd[B_];
__device__ int   g_done;            // gemm-completion counter (reset by k_selfix)

__device__ __forceinline__ float sigm(float x) { return 1.0f / (1.0f + expf(-x)); }
__device__ __forceinline__ float clip01(float x) { return fminf(fmaxf(x, 0.0f), 1.0f); }
__device__ __forceinline__ float dot4(float4 a, float4 b) {
    return a.x * b.x + a.y * b.y + a.z * b.z + a.w * b.w;
}

// =====================================================================
// Mega-kernel: block roles
//   [0, 256)            : GEMM (candidate key/value, tanh) -> signals g_done
//   [256, 768)          : heads (4 scalar gemvs, 2 batches/block)
//   [768, 4864)         : score_vals streaming (8 warps x 4 rows)
//   [4864, 8960)        : score_keys streaming (waits for g_done == 256)
// GEMM blocks have the lowest bids => all resident in wave 1 (wave-1
// capacity ~592 blocks at 4 blocks/SM), so keys blocks can never occupy
// the chip before the producers => flag-wait cannot deadlock.
// =====================================================================
#define NG_ 256
#define NH_ 512
#define NV_ 4096
#define NK_ 4096
#define MT_ 64
#define NT_ 64
#define KT_ 16

__global__ void __launch_bounds__(256, 4) k_mega(
    const float* __restrict__ hidden,
    const float* __restrict__ wvals,
    const float* __restrict__ wkeys,
    const float* __restrict__ Wk, const float* __restrict__ bk,
    const float* __restrict__ Wv, const float* __restrict__ bv,
    const float* __restrict__ Wwr, const float* __restrict__ bwr,
    const float* __restrict__ Wmg, const float* __restrict__ bmg,
    const float* __restrict__ Wbd, const float* __restrict__ bbd,
    const float* __restrict__ Wim, const float* __restrict__ bim,
    const float* __restrict__ Woc, const float* __restrict__ boc,
    const float* __restrict__ Wpr, const float* __restrict__ bpr,
    float* __restrict__ out)
{
    const int bid = blockIdx.x;
    const int tid = threadIdx.x;

    if (bid < NG_) {
        // ------------------- GEMM role -------------------
        const int mx = bid & 15;
        const int ny = (bid >> 4) & 7;
        const int z = bid >> 7;
        const float* __restrict__ W    = z ? Wv : Wk;
        const float* __restrict__ bias = z ? bv : bk;
        float* outp = z ? g_cv : g_ck;

        const int tx = tid & 15;
        const int ty = tid >> 4;
        const int m0 = mx * MT_;
        const int n0 = ny * NT_;

        __shared__ __align__(16) float As[2][KT_][MT_];
        __shared__ __align__(16) float Bs[2][KT_][NT_];

        const int ar = tid >> 2;
        const int aq = tid & 3;
        const int br = tid >> 4;
        const int bc = tid & 15;

        const float* Aptr = hidden + (size_t)(m0 + ar) * D_ + aq * 4;
        const float* Bptr = W + (size_t)br * D_ + n0 + bc * 4;

        float4 ra = *reinterpret_cast<const float4*>(Aptr);
        float4 rb = *reinterpret_cast<const float4*>(Bptr);

        float acc[4][4] = {};

        As[0][aq * 4 + 0][ar] = ra.x;
        As[0][aq * 4 + 1][ar] = ra.y;
        As[0][aq * 4 + 2][ar] = ra.z;
        As[0][aq * 4 + 3][ar] = ra.w;
        *reinterpret_cast<float4*>(&Bs[0][br][bc * 4]) = rb;
        __syncthreads();

        const int NCH = D_ / KT_;  // 32
#pragma unroll 1
        for (int kc = 0; kc < NCH; kc++) {
            const int cur = kc & 1;
            if (kc + 1 < NCH) {
                ra = *reinterpret_cast<const float4*>(Aptr + (kc + 1) * KT_);
                rb = *reinterpret_cast<const float4*>(Bptr + (size_t)(kc + 1) * KT_ * D_);
            }
#pragma unroll
            for (int kk = 0; kk < KT_; kk++) {
                float4 a = *reinterpret_cast<const float4*>(&As[cur][kk][ty * 4]);
                float4 b = *reinterpret_cast<const float4*>(&Bs[cur][kk][tx * 4]);
                float av[4] = {a.x, a.y, a.z, a.w};
                float bw[4] = {b.x, b.y, b.z, b.w};
#pragma unroll
                for (int i = 0; i < 4; i++)
#pragma unroll
                    for (int j = 0; j < 4; j++)
                        acc[i][j] += av[i] * bw[j];
            }
            if (kc + 1 < NCH) {
                const int nxt = cur ^ 1;
                As[nxt][aq * 4 + 0][ar] = ra.x;
                As[nxt][aq * 4 + 1][ar] = ra.y;
                As[nxt][aq * 4 + 2][ar] = ra.z;
                As[nxt][aq * 4 + 3][ar] = ra.w;
                *reinterpret_cast<float4*>(&Bs[nxt][br][bc * 4]) = rb;
                __syncthreads();
            }
        }

        const float4 bv4 = *reinterpret_cast<const float4*>(bias + n0 + tx * 4);
#pragma unroll
        for (int i = 0; i < 4; i++) {
            float4 o;
            o.x = tanhf(acc[i][0] + bv4.x);
            o.y = tanhf(acc[i][1] + bv4.y);
            o.z = tanhf(acc[i][2] + bv4.z);
            o.w = tanhf(acc[i][3] + bv4.w);
            *reinterpret_cast<float4*>(outp + (size_t)(m0 + ty * 4 + i) * D_ + n0 + tx * 4) = o;
        }

        // signal completion of this gemm block
        __syncthreads();
        if (tid == 0) {
            __threadfence();
            atomicAdd(&g_done, 1);
        }
    } else if (bid < NG_ + NH_) {
        // ------------------- heads role (2 batches per block) -------------------
        const int g = tid >> 7;
        const int t = tid & 127;
        const int b = (bid - NG_) * 2 + g;

        float4 h = reinterpret_cast<const float4*>(hidden + (size_t)b * D_)[t];
        float4 w;
        w = reinterpret_cast<const float4*>(Wwr)[t];
        float pwr = dot4(h, w);
        w = reinterpret_cast<const float4*>(Wmg)[t];
        float pmg = dot4(h, w);
        w = reinterpret_cast<const float4*>(Wbd)[t];
        float pbd = dot4(h, w);
        w = reinterpret_cast<const float4*>(Wim)[t];
        float pim = dot4(h, w);

#pragma unroll
        for (int o = 16; o; o >>= 1) {
            pwr += __shfl_xor_sync(0xffffffffu, pwr, o);
            pmg += __shfl_xor_sync(0xffffffffu, pmg, o);
            pbd += __shfl_xor_sync(0xffffffffu, pbd, o);
            pim += __shfl_xor_sync(0xffffffffu, pim, o);
        }
        __shared__ float red[2][4][4];
        if ((t & 31) == 0) {
            int wi = t >> 5;
            red[g][wi][0] = pwr; red[g][wi][1] = pmg;
            red[g][wi][2] = pbd; red[g][wi][3] = pim;
        }
        __syncthreads();
        if (t == 0) {
            float dwr = red[g][0][0] + red[g][1][0] + red[g][2][0] + red[g][3][0];
            float dmg = red[g][0][1] + red[g][1][1] + red[g][2][1] + red[g][3][1];
            float dbd = red[g][0][2] + red[g][1][2] + red[g][2][2] + red[g][3][2];
            float dIm = red[g][0][3] + red[g][1][3] + red[g][2][3] + red[g][3][3];
            float ws = sigm(dwr + bwr[0]);
            g_ws[b] = ws;
            out[O3_ + b] = ws;
            g_im[b] = sigm(dIm + bim[0]);
            g_hmg[b] = dmg + bmg[0];
            g_hbd[b] = dbd + bbd[0];
        }
    } else if (bid < NG_ + NH_ + NV_) {
        // ------------------- score_vals role -------------------
        const int w = (bid - NG_ - NH_) * 8 + (tid >> 5);
        const int lane = tid & 31;
        const int r0 = w * 4;

        const float4* wo = reinterpret_cast<const float4*>(Woc);
        const float4* wp = reinterpret_cast<const float4*>(Wpr);
        float4 o0 = wo[lane], o1 = wo[lane + 32], o2 = wo[lane + 64], o3 = wo[lane + 96];
        float4 q0 = wp[lane], q1 = wp[lane + 32], q2 = wp[lane + 64], q3 = wp[lane + 96];
        const float bocv = __ldg(boc);
        const float bprv = __ldg(bpr);

#pragma unroll
        for (int p = 0; p < 2; p++) {
            const int ra = r0 + 2 * p;
            const float4* va = reinterpret_cast<const float4*>(wvals + (size_t)ra * D_);
            const float4* vb = va + 128;
            float4 a0 = va[lane], a1 = va[lane + 32], a2 = va[lane + 64], a3 = va[lane + 96];
            float4 e0 = vb[lane], e1 = vb[lane + 32], e2 = vb[lane + 64], e3 = vb[lane + 96];

            float4* oa = reinterpret_cast<float4*>(out + O1_ + (size_t)ra * D_);
            float4* ob = oa + 128;
            oa[lane] = a0; oa[lane + 32] = a1; oa[lane + 64] = a2; oa[lane + 96] = a3;
            ob[lane] = e0; ob[lane + 32] = e1; ob[lane + 64] = e2; ob[lane + 96] = e3;

            float pa0 = dot4(a0, a0) + dot4(a1, a1) + dot4(a2, a2) + dot4(a3, a3);
            float pa1 = dot4(a0, o0) + dot4(a1, o1) + dot4(a2, o2) + dot4(a3, o3);
            float pa2 = dot4(a0, q0) + dot4(a1, q1) + dot4(a2, q2) + dot4(a3, q3);
            float pb0 = dot4(e0, e0) + dot4(e1, e1) + dot4(e2, e2) + dot4(e3, e3);
            float pb1 = dot4(e0, o0) + dot4(e1, o1) + dot4(e2, o2) + dot4(e3, o3);
            float pb2 = dot4(e0, q0) + dot4(e1, q1) + dot4(e2, q2) + dot4(e3, q3);
#pragma unroll
            for (int o = 16; o; o >>= 1) {
                pa0 += __shfl_xor_sync(0xffffffffu, pa0, o);
                pa1 += __shfl_xor_sync(0xffffffffu, pa1, o);
                pa2 += __shfl_xor_sync(0xffffffffu, pa2, o);
                pb0 += __shfl_xor_sync(0xffffffffu, pb0, o);
                pb1 += __shfl_xor_sync(0xffffffffu, pb1, o);
                pb2 += __shfl_xor_sync(0xffffffffu, pb2, o);
            }
            if (lane == 0) {
                float nocc = clip01(sqrtf(pa0) * 0.04419417382415922f);  // / sqrt(512)
                g_occ[ra] = clip01(0.5f * sigm(pa1 + bocv) + 0.5f * nocc);
                g_lprot[ra] = sigm(pa2 + bprv);
                nocc = clip01(sqrtf(pb0) * 0.04419417382415922f);
                g_occ[ra + 1] = clip01(0.5f * sigm(pb1 + bocv) + 0.5f * nocc);
                g_lprot[ra + 1] = sigm(pb2 + bprv);
            }
        }
    } else {
        // ------------------- score_keys role (waits on gemm flag) -------------------
        if (tid == 0) {
            while (atomicAdd(&g_done, 0) < NG_) __nanosleep(128);
        }
        __syncthreads();
        __threadfence();

        const int w = (bid - NG_ - NH_ - NV_) * 8 + (tid >> 5);
        const int lane = tid & 31;
        const int r0 = w * 4;
        const int b = r0 >> 7;

        const float4* cr = reinterpret_cast<const float4*>(g_ck + (size_t)b * D_);
        float4 c0 = cr[lane], c1 = cr[lane + 32], c2 = cr[lane + 64], c3 = cr[lane + 96];

        float pss = dot4(c0, c0) + dot4(c1, c1) + dot4(c2, c2) + dot4(c3, c3);
#pragma unroll
        for (int o = 16; o; o >>= 1) pss += __shfl_xor_sync(0xffffffffu, pss, o);
        const float invnc = 1.0f / fmaxf(sqrtf(pss), 1e-6f);

#pragma unroll
        for (int p = 0; p < 2; p++) {
            const int ra = r0 + 2 * p;
            const float4* ka = reinterpret_cast<const float4*>(wkeys + (size_t)ra * D_);
            const float4* kb = ka + 128;
            float4 a0 = ka[lane], a1 = ka[lane + 32], a2 = ka[lane + 64], a3 = ka[lane + 96];
            float4 e0 = kb[lane], e1 = kb[lane + 32], e2 = kb[lane + 64], e3 = kb[lane + 96];

            float4* oa = reinterpret_cast<float4*>(out + (size_t)ra * D_);
            float4* ob = oa + 128;
            oa[lane] = a0; oa[lane + 32] = a1; oa[lane + 64] = a2; oa[lane + 96] = a3;
            ob[lane] = e0; ob[lane + 32] = e1; ob[lane + 64] = e2; ob[lane + 96] = e3;

            float pa0 = dot4(a0, c0) + dot4(a1, c1) + dot4(a2, c2) + dot4(a3, c3);
            float pa1 = dot4(a0, a0) + dot4(a1, a1) + dot4(a2, a2) + dot4(a3, a3);
            float pb0 = dot4(e0, c0) + dot4(e1, c1) + dot4(e2, c2) + dot4(e3, c3);
            float pb1 = dot4(e0, e0) + dot4(e1, e1) + dot4(e2, e2) + dot4(e3, e3);
#pragma unroll
            for (int o = 16; o; o >>= 1) {
                pa0 += __shfl_xor_sync(0xffffffffu, pa0, o);
                pa1 += __shfl_xor_sync(0xffffffffu, pa1, o);
                pb0 += __shfl_xor_sync(0xffffffffu, pb0, o);
                pb1 += __shfl_xor_sync(0xffffffffu, pb1, o);
            }
            if (lane == 0) {
                g_sim[ra]     = pa0 * invnc / fmaxf(sqrtf(pa1), 1e-6f);
                g_sim[ra + 1] = pb0 * invnc / fmaxf(sqrtf(pb1), 1e-6f);
            }
        }
    }
}

// =====================================================================
// Kernel 2: per-batch selection + small outputs + target-row fixup.
// Also resets g_done for the next (graph-replayed) call.
// =====================================================================
__global__ void __launch_bounds__(128) k_selfix(
    const float* __restrict__ wprot, const float* __restrict__ wusage,
    const float* __restrict__ wage,
    const float* __restrict__ wkeys, const float* __restrict__ wvals,
    float* __restrict__ out)
{
    const int b = blockIdx.x;
    const int n = threadIdx.x;
    const int idx = b * N_ + n;

    if (b == 0 && n == 0) g_done = 0;   // reset producer flag for next call

    float sim = g_sim[idx];
    float occ = g_occ[idx];
    float lp  = g_lprot[idx];
    float wp  = wprot[idx];
    float ep = clip01(0.4f * lp + 0.6f * wp);
    float eu = clip01(0.5f * occ + 0.5f * wusage[idx]);
    float ea = clip01(wage[idx]);
    float rs = 1.15f * (1.0f - occ) + 0.85f * (1.0f - ep) + 0.65f * ea
             + 0.45f * (1.0f - eu) + 0.25f * (1.0f - sim);

    __shared__ float sS[N_], sO[N_], sU[N_], sA[N_], sE[N_];
    sS[n] = sim; sO[n] = occ; sU[n] = eu; sA[n] = ea; sE[n] = ep;

    float v1 = sim; int i1 = n;
    float v2 = rs;  int i2 = n;
#pragma unroll
    for (int o = 16; o; o >>= 1) {
        float ov = __shfl_down_sync(0xffffffffu, v1, o);
        int   oi = __shfl_down_sync(0xffffffffu, i1, o);
        if (ov > v1 || (ov == v1 && oi < i1)) { v1 = ov; i1 = oi; }
        ov = __shfl_down_sync(0xffffffffu, v2, o);
        oi = __shfl_down_sync(0xffffffffu, i2, o);
        if (ov > v2 || (ov == v2 && oi < i2)) { v2 = ov; i2 = oi; }
    }
    __shared__ float wv1[4], wv2[4];
    __shared__ int wi1[4], wi2[4];
    if ((n & 31) == 0) {
        int w = n >> 5;
        wv1[w] = v1; wi1[w] = i1; wv2[w] = v2; wi2[w] = i2;
    }
    __syncthreads();

    __shared__ int sh_tgt;
    __shared__ float sh_owt, sh_bf, sh_ak, sh_av;
    if (n == 0) {
        float bv = wv1[0]; int bi = wi1[0];
#pragma unroll
        for (int w = 1; w < 4; w++)
            if (wv1[w] > bv || (wv1[w] == bv && wi1[w] < bi)) { bv = wv1[w]; bi = wi1[w]; }
        int mi = bi;
        float rbv = wv2[0]; int ri = wi2[0];
#pragma unroll
        for (int w = 1; w < 4; w++)
            if (wv2[w] > rbv || (wv2[w] == rbv && wi2[w] < ri)) { rbv = wv2[w]; ri = wi2[w]; }

        float ms = sS[mi], mo = sO[mi], mu = sU[mi], ma = sA[mi];
        float mp = sigm(g_hmg[b] + 2.4f * ms + 1.6f * (mo - 0.5f)
                        + 1.0f * (mu - 0.5f) - 0.8f * ma);
        bool um = (mp >= 0.5f) && (ms > 0.55f) && (mo > 0.35f);
        int tgt = um ? mi : ri;
        float bind = sigm(g_hbd[b] + 2.2f * ms);
        float conflict = clip01(1.0f - sS[tgt]);
        float owt = (0.15f + 0.85f * g_ws[b]) * (1.0f - 0.65f * sE[tgt] * conflict);
        float im = g_im[b];
        float km = um ? (0.22f + 0.38f * bind) : (0.78f + 0.18f * bind);
        float vm = um ? (0.45f + 0.35f * im) : (0.75f + 0.20f * im);

        out[O4_ + b] = mp;
        out[O5_ + b] = bind;
        out[O6_ + b] = owt * (1.0f / N_);
        out[O8_ + b] = ms;
        sh_tgt = tgt;
        sh_owt = owt;
        sh_bf = 0.5f + 0.5f * im;
        sh_ak = owt * km;
        sh_av = owt * vm;
    }
    __syncthreads();

    float ow = (n == sh_tgt) ? sh_owt : 0.0f;
    out[O9_ + idx] = ow;
    float up = clip01(wp * 0.98f + ow * sh_bf);
    out[O2_ + idx] = up;

    float s = up;
#pragma unroll
    for (int o = 16; o; o >>= 1) s += __shfl_xor_sync(0xffffffffu, s, o);
    __shared__ float ss4[4];
    if ((n & 31) == 0) ss4[n >> 5] = s;
    __syncthreads();
    if (n == 0) out[O7_ + b] = (ss4[0] + ss4[1] + ss4[2] + ss4[3]) * (1.0f / N_);

    // ---- fixup of the single target row in both big outputs ----
    const int t = sh_tgt;
    const float ak = sh_ak;
    const float av = sh_av;
    const size_t roff = ((size_t)b * N_ + t) * D_;

    float4 k = reinterpret_cast<const float4*>(wkeys + roff)[n];
    float4 c = reinterpret_cast<const float4*>(g_ck + (size_t)b * D_)[n];
    float4 ok;
    ok.x = k.x + ak * (c.x - k.x);
    ok.y = k.y + ak * (c.y - k.y);
    ok.z = k.z + ak * (c.z - k.z);
    ok.w = k.w + ak * (c.w - k.w);
    reinterpret_cast<float4*>(out + roff)[n] = ok;

    float4 v = reinterpret_cast<const float4*>(wvals + roff)[n];
    float4 cv = reinterpret_cast<const float4*>(g_cv + (size_t)b * D_)[n];
    float4 ov;
    ov.x = v.x + av * (cv.x - v.x);
    ov.y = v.y + av * (cv.y - v.y);
    ov.z = v.z + av * (cv.z - v.z);
    ov.w = v.w + av * (cv.w - v.w);
    reinterpret_cast<float4*>(out + O1_ + roff)[n] = ov;
}

// =====================================================================
extern "C" void kernel_launch(void* const* d_in, const int* in_sizes, int n_in,
                              void* d_out, int out_size)
{
    const float* hidden = (const float*)d_in[0];
    const float* wkeys  = (const float*)d_in[1];
    const float* wvals  = (const float*)d_in[2];
    const float* wprot  = (const float*)d_in[3];
    const float* wusage = (const float*)d_in[4];
    const float* wage   = (const float*)d_in[5];
    const float* Wk  = (const float*)d_in[6];
    const float* bk  = (const float*)d_in[7];
    const float* Wv  = (const float*)d_in[8];
    const float* bv  = (const float*)d_in[9];
    const float* Wwr = (const float*)d_in[10];
    const float* bwr = (const float*)d_in[11];
    const float* Wmg = (const float*)d_in[12];
    const float* bmg = (const float*)d_in[13];
    const float* Wbd = (const float*)d_in[14];
    const float* bbd = (const float*)d_in[15];
    const float* Wim = (const float*)d_in[16];
    const float* bim = (const float*)d_in[17];
    const float* Woc = (const float*)d_in[18];
    const float* boc = (const float*)d_in[19];
    const float* Wpr = (const float*)d_in[20];
    const float* bpr = (const float*)d_in[21];
    float* out = (float*)d_out;

    k_mega<<<NG_ + NH_ + NV_ + NK_, 256>>>(hidden, wvals, wkeys, Wk, bk, Wv, bv,
                                           Wwr, bwr, Wmg, bmg, Wbd, bbd, Wim, bim,
                                           Woc, boc, Wpr, bpr, out);
    k_selfix<<<B_, 128>>>(wprot, wusage, wage, wkeys, wvals, out);
}

// round 9
// speedup vs baseline: 1.1250x; 1.1250x over previous
#include <cuda_runtime.h>
#include <math.h>

#define B_ 1024
#define N_ 128
#define D_ 512

// ---- output layout (float32, concatenated in reference return order) ----
__device__ __host__ constexpr size_t KD_ = (size_t)B_ * N_ * D_;   // 67108864
__device__ __host__ constexpr size_t O1_ = KD_;                    // updated_values
__device__ __host__ constexpr size_t O2_ = 2 * KD_;                // updated_protection (B*N)
__device__ __host__ constexpr size_t O3_ = O2_ + (size_t)B_ * N_;  // write_strength (B)
__device__ __host__ constexpr size_t O4_ = O3_ + B_;               // merge_preference (B)
__device__ __host__ constexpr size_t O5_ = O4_ + B_;               // binding_strength (B)
__device__ __host__ constexpr size_t O6_ = O5_ + B_;               // overwrite.mean (B)
__device__ __host__ constexpr size_t O7_ = O6_ + B_;               // updated_protection.mean (B)
__device__ __host__ constexpr size_t O8_ = O7_ + B_;               // max_similarity (B)
__device__ __host__ constexpr size_t O9_ = O8_ + B_;               // overwrite (B*N)

// ---- scratch (__device__ globals; no allocations allowed) ----
__device__ float g_ck[B_ * D_];     // candidate_key (tanh)
__device__ float g_cv[B_ * D_];     // candidate_value (tanh)
__device__ float g_sim[B_ * N_];
__device__ float g_occ[B_ * N_];
__device__ float g_lprot[B_ * N_];
__device__ float g_ws[B_];
__device__ float g_im[B_];
__device__ float g_hmg[B_];
__device__ float g_hbd[B_];

__device__ __forceinline__ float sigm(float x) { return 1.0f / (1.0f + expf(-x)); }
__device__ __forceinline__ float clip01(float x) { return fminf(fmaxf(x, 0.0f), 1.0f); }
__device__ __forceinline__ float dot4(float4 a, float4 b) {
    return a.x * b.x + a.y * b.y + a.z * b.z + a.w * b.w;
}

// =====================================================================
// Mega-kernel: block roles
//   [0, 256)        : GEMM (candidate key/value, tanh) - single-buffered,
//                     low-register variant so the whole kernel fits 64 regs
//   [256, 768)      : heads (4 scalar gemvs, 2 batches/block)
//   [768, 4864)     : score_vals streaming (8 warps x 4 rows)
// All roles are mutually independent.
// =====================================================================
#define NG_ 256
#define NH_ 512
#define NV_ 4096
#define MT_ 64
#define NT_ 64
#define KT_ 16

__global__ void __launch_bounds__(256, 4) k_mega(
    const float* __restrict__ hidden,
    const float* __restrict__ wvals,
    const float* __restrict__ Wk, const float* __restrict__ bk,
    const float* __restrict__ Wv, const float* __restrict__ bv,
    const float* __restrict__ Wwr, const float* __restrict__ bwr,
    const float* __restrict__ Wmg, const float* __restrict__ bmg,
    const float* __restrict__ Wbd, const float* __restrict__ bbd,
    const float* __restrict__ Wim, const float* __restrict__ bim,
    const float* __restrict__ Woc, const float* __restrict__ boc,
    const float* __restrict__ Wpr, const float* __restrict__ bpr,
    float* __restrict__ out)
{
    const int bid = blockIdx.x;
    const int tid = threadIdx.x;

    if (bid < NG_) {
        // ------------------- GEMM role (single-buffered, low-reg) -------------------
        const int mx = bid & 15;
        const int ny = (bid >> 4) & 7;
        const int z = bid >> 7;
        const float* __restrict__ W    = z ? Wv : Wk;
        const float* __restrict__ bias = z ? bv : bk;
        float* outp = z ? g_cv : g_ck;

        const int tx = tid & 15;
        const int ty = tid >> 4;
        const int m0 = mx * MT_;
        const int n0 = ny * NT_;

        __shared__ __align__(16) float As[KT_][MT_];
        __shared__ __align__(16) float Bs[KT_][NT_];

        const int ar = tid >> 2;
        const int aq = tid & 3;
        const int br = tid >> 4;
        const int bc = tid & 15;

        const float* Aptr = hidden + (size_t)(m0 + ar) * D_ + aq * 4;
        const float* Bptr = W + (size_t)br * D_ + n0 + bc * 4;

        float acc[4][4] = {};

        const int NCH = D_ / KT_;  // 32
#pragma unroll 1
        for (int kc = 0; kc < NCH; kc++) {
            float4 ra = *reinterpret_cast<const float4*>(Aptr + kc * KT_);
            float4 rb = *reinterpret_cast<const float4*>(Bptr + (size_t)kc * KT_ * D_);
            __syncthreads();   // previous chunk's compute done before overwrite
            As[aq * 4 + 0][ar] = ra.x;
            As[aq * 4 + 1][ar] = ra.y;
            As[aq * 4 + 2][ar] = ra.z;
            As[aq * 4 + 3][ar] = ra.w;
            *reinterpret_cast<float4*>(&Bs[br][bc * 4]) = rb;
            __syncthreads();
#pragma unroll
            for (int kk = 0; kk < KT_; kk++) {
                float4 a = *reinterpret_cast<const float4*>(&As[kk][ty * 4]);
                float4 b = *reinterpret_cast<const float4*>(&Bs[kk][tx * 4]);
                float av[4] = {a.x, a.y, a.z, a.w};
                float bw[4] = {b.x, b.y, b.z, b.w};
#pragma unroll
                for (int i = 0; i < 4; i++)
#pragma unroll
                    for (int j = 0; j < 4; j++)
                        acc[i][j] += av[i] * bw[j];
            }
        }

        const float4 bv4 = *reinterpret_cast<const float4*>(bias + n0 + tx * 4);
#pragma unroll
        for (int i = 0; i < 4; i++) {
            float4 o;
            o.x = tanhf(acc[i][0] + bv4.x);
            o.y = tanhf(acc[i][1] + bv4.y);
            o.z = tanhf(acc[i][2] + bv4.z);
            o.w = tanhf(acc[i][3] + bv4.w);
            *reinterpret_cast<float4*>(outp + (size_t)(m0 + ty * 4 + i) * D_ + n0 + tx * 4) = o;
        }
    } else if (bid < NG_ + NH_) {
        // ------------------- heads role (2 batches per block) -------------------
        const int g = tid >> 7;
        const int t = tid & 127;
        const int b = (bid - NG_) * 2 + g;

        float4 h = reinterpret_cast<const float4*>(hidden + (size_t)b * D_)[t];
        float4 w;
        w = reinterpret_cast<const float4*>(Wwr)[t];
        float pwr = dot4(h, w);
        w = reinterpret_cast<const float4*>(Wmg)[t];
        float pmg = dot4(h, w);
        w = reinterpret_cast<const float4*>(Wbd)[t];
        float pbd = dot4(h, w);
        w = reinterpret_cast<const float4*>(Wim)[t];
        float pim = dot4(h, w);

#pragma unroll
        for (int o = 16; o; o >>= 1) {
            pwr += __shfl_xor_sync(0xffffffffu, pwr, o);
            pmg += __shfl_xor_sync(0xffffffffu, pmg, o);
            pbd += __shfl_xor_sync(0xffffffffu, pbd, o);
            pim += __shfl_xor_sync(0xffffffffu, pim, o);
        }
        __shared__ float red[2][4][4];
        if ((t & 31) == 0) {
            int wi = t >> 5;
            red[g][wi][0] = pwr; red[g][wi][1] = pmg;
            red[g][wi][2] = pbd; red[g][wi][3] = pim;
        }
        __syncthreads();
        if (t == 0) {
            float dwr = red[g][0][0] + red[g][1][0] + red[g][2][0] + red[g][3][0];
            float dmg = red[g][0][1] + red[g][1][1] + red[g][2][1] + red[g][3][1];
            float dbd = red[g][0][2] + red[g][1][2] + red[g][2][2] + red[g][3][2];
            float dIm = red[g][0][3] + red[g][1][3] + red[g][2][3] + red[g][3][3];
            float ws = sigm(dwr + bwr[0]);
            g_ws[b] = ws;
            out[O3_ + b] = ws;
            g_im[b] = sigm(dIm + bim[0]);
            g_hmg[b] = dmg + bmg[0];
            g_hbd[b] = dbd + bbd[0];
        }
    } else {
        // ------------------- score_vals role -------------------
        const int w = (bid - NG_ - NH_) * 8 + (tid >> 5);
        const int lane = tid & 31;
        const int r0 = w * 4;

        const float4* wo = reinterpret_cast<const float4*>(Woc);
        const float4* wp = reinterpret_cast<const float4*>(Wpr);
        float4 o0 = wo[lane], o1 = wo[lane + 32], o2 = wo[lane + 64], o3 = wo[lane + 96];
        float4 q0 = wp[lane], q1 = wp[lane + 32], q2 = wp[lane + 64], q3 = wp[lane + 96];
        const float bocv = __ldg(boc);
        const float bprv = __ldg(bpr);

#pragma unroll
        for (int p = 0; p < 2; p++) {
            const int ra = r0 + 2 * p;
            const float4* va = reinterpret_cast<const float4*>(wvals + (size_t)ra * D_);
            const float4* vb = va + 128;
            float4 a0 = va[lane], a1 = va[lane + 32], a2 = va[lane + 64], a3 = va[lane + 96];
            float4 e0 = vb[lane], e1 = vb[lane + 32], e2 = vb[lane + 64], e3 = vb[lane + 96];

            float4* oa = reinterpret_cast<float4*>(out + O1_ + (size_t)ra * D_);
            float4* ob = oa + 128;
            oa[lane] = a0; oa[lane + 32] = a1; oa[lane + 64] = a2; oa[lane + 96] = a3;
            ob[lane] = e0; ob[lane + 32] = e1; ob[lane + 64] = e2; ob[lane + 96] = e3;

            float pa0 = dot4(a0, a0) + dot4(a1, a1) + dot4(a2, a2) + dot4(a3, a3);
            float pa1 = dot4(a0, o0) + dot4(a1, o1) + dot4(a2, o2) + dot4(a3, o3);
            float pa2 = dot4(a0, q0) + dot4(a1, q1) + dot4(a2, q2) + dot4(a3, q3);
            float pb0 = dot4(e0, e0) + dot4(e1, e1) + dot4(e2, e2) + dot4(e3, e3);
            float pb1 = dot4(e0, o0) + dot4(e1, o1) + dot4(e2, o2) + dot4(e3, o3);
            float pb2 = dot4(e0, q0) + dot4(e1, q1) + dot4(e2, q2) + dot4(e3, q3);
#pragma unroll
            for (int o = 16; o; o >>= 1) {
                pa0 += __shfl_xor_sync(0xffffffffu, pa0, o);
                pa1 += __shfl_xor_sync(0xffffffffu, pa1, o);
                pa2 += __shfl_xor_sync(0xffffffffu, pa2, o);
                pb0 += __shfl_xor_sync(0xffffffffu, pb0, o);
                pb1 += __shfl_xor_sync(0xffffffffu, pb1, o);
                pb2 += __shfl_xor_sync(0xffffffffu, pb2, o);
            }
            if (lane == 0) {
                float nocc = clip01(sqrtf(pa0) * 0.04419417382415922f);  // / sqrt(512)
                g_occ[ra] = clip01(0.5f * sigm(pa1 + bocv) + 0.5f * nocc);
                g_lprot[ra] = sigm(pa2 + bprv);
                nocc = clip01(sqrtf(pb0) * 0.04419417382415922f);
                g_occ[ra + 1] = clip01(0.5f * sigm(pb1 + bocv) + 0.5f * nocc);
                g_lprot[ra + 1] = sigm(pb2 + bprv);
            }
        }
    }
}

// =====================================================================
// Kernel 2: streaming pass over working_keys. One warp -> 4 rows.
// =====================================================================
__global__ void __launch_bounds__(256) k_score_keys(
    const float* __restrict__ wkeys, float* __restrict__ out)
{
    const int w = blockIdx.x * 8 + (threadIdx.x >> 5);
    const int lane = threadIdx.x & 31;
    const int r0 = w * 4;
    const int b = r0 >> 7;

    const float4* cr = reinterpret_cast<const float4*>(g_ck + (size_t)b * D_);
    float4 c0 = cr[lane], c1 = cr[lane + 32], c2 = cr[lane + 64], c3 = cr[lane + 96];

    float pss = dot4(c0, c0) + dot4(c1, c1) + dot4(c2, c2) + dot4(c3, c3);
#pragma unroll
    for (int o = 16; o; o >>= 1) pss += __shfl_xor_sync(0xffffffffu, pss, o);
    const float invnc = 1.0f / fmaxf(sqrtf(pss), 1e-6f);

#pragma unroll
    for (int p = 0; p < 2; p++) {
        const int ra = r0 + 2 * p;
        const float4* ka = reinterpret_cast<const float4*>(wkeys + (size_t)ra * D_);
        const float4* kb = ka + 128;
        float4 a0 = ka[lane], a1 = ka[lane + 32], a2 = ka[lane + 64], a3 = ka[lane + 96];
        float4 e0 = kb[lane], e1 = kb[lane + 32], e2 = kb[lane + 64], e3 = kb[lane + 96];

        float4* oa = reinterpret_cast<float4*>(out + (size_t)ra * D_);
        float4* ob = oa + 128;
        oa[lane] = a0; oa[lane + 32] = a1; oa[lane + 64] = a2; oa[lane + 96] = a3;
        ob[lane] = e0; ob[lane + 32] = e1; ob[lane + 64] = e2; ob[lane + 96] = e3;

        float pa0 = dot4(a0, c0) + dot4(a1, c1) + dot4(a2, c2) + dot4(a3, c3);
        float pa1 = dot4(a0, a0) + dot4(a1, a1) + dot4(a2, a2) + dot4(a3, a3);
        float pb0 = dot4(e0, c0) + dot4(e1, c1) + dot4(e2, c2) + dot4(e3, c3);
        float pb1 = dot4(e0, e0) + dot4(e1, e1) + dot4(e2, e2) + dot4(e3, e3);
#pragma unroll
        for (int o = 16; o; o >>= 1) {
            pa0 += __shfl_xor_sync(0xffffffffu, pa0, o);
            pa1 += __shfl_xor_sync(0xffffffffu, pa1, o);
            pb0 += __shfl_xor_sync(0xffffffffu, pb0, o);
            pb1 += __shfl_xor_sync(0xffffffffu, pb1, o);
        }
        if (lane == 0) {
            g_sim[ra]     = pa0 * invnc / fmaxf(sqrtf(pa1), 1e-6f);
            g_sim[ra + 1] = pb0 * invnc / fmaxf(sqrtf(pb1), 1e-6f);
        }
    }
}

// =====================================================================
// Kernel 3: per-batch selection + small outputs + target-row fixup.
// =====================================================================
__global__ void __launch_bounds__(128) k_selfix(
    const float* __restrict__ wprot, const float* __restrict__ wusage,
    const float* __restrict__ wage,
    const float* __restrict__ wkeys, const float* __restrict__ wvals,
    float* __restrict__ out)
{
    const int b = blockIdx.x;
    const int n = threadIdx.x;
    const int idx = b * N_ + n;

    float sim = g_sim[idx];
    float occ = g_occ[idx];
    float lp  = g_lprot[idx];
    float wp  = wprot[idx];
    float ep = clip01(0.4f * lp + 0.6f * wp);
    float eu = clip01(0.5f * occ + 0.5f * wusage[idx]);
    float ea = clip01(wage[idx]);
    float rs = 1.15f * (1.0f - occ) + 0.85f * (1.0f - ep) + 0.65f * ea
             + 0.45f * (1.0f - eu) + 0.25f * (1.0f - sim);

    __shared__ float sS[N_], sO[N_], sU[N_], sA[N_], sE[N_];
    sS[n] = sim; sO[n] = occ; sU[n] = eu; sA[n] = ea; sE[n] = ep;

    float v1 = sim; int i1 = n;
    float v2 = rs;  int i2 = n;
#pragma unroll
    for (int o = 16; o; o >>= 1) {
        float ov = __shfl_down_sync(0xffffffffu, v1, o);
        int   oi = __shfl_down_sync(0xffffffffu, i1, o);
        if (ov > v1 || (ov == v1 && oi < i1)) { v1 = ov; i1 = oi; }
        ov = __shfl_down_sync(0xffffffffu, v2, o);
        oi = __shfl_down_sync(0xffffffffu, i2, o);
        if (ov > v2 || (ov == v2 && oi < i2)) { v2 = ov; i2 = oi; }
    }
    __shared__ float wv1[4], wv2[4];
    __shared__ int wi1[4], wi2[4];
    if ((n & 31) == 0) {
        int w = n >> 5;
        wv1[w] = v1; wi1[w] = i1; wv2[w] = v2; wi2[w] = i2;
    }
    __syncthreads();

    __shared__ int sh_tgt;
    __shared__ float sh_owt, sh_bf, sh_ak, sh_av;
    if (n == 0) {
        float bv = wv1[0]; int bi = wi1[0];
#pragma unroll
        for (int w = 1; w < 4; w++)
            if (wv1[w] > bv || (wv1[w] == bv && wi1[w] < bi)) { bv = wv1[w]; bi = wi1[w]; }
        int mi = bi;
        float rbv = wv2[0]; int ri = wi2[0];
#pragma unroll
        for (int w = 1; w < 4; w++)
            if (wv2[w] > rbv || (wv2[w] == rbv && wi2[w] < ri)) { rbv = wv2[w]; ri = wi2[w]; }

        float ms = sS[mi], mo = sO[mi], mu = sU[mi], ma = sA[mi];
        float mp = sigm(g_hmg[b] + 2.4f * ms + 1.6f * (mo - 0.5f)
                        + 1.0f * (mu - 0.5f) - 0.8f * ma);
        bool um = (mp >= 0.5f) && (ms > 0.55f) && (mo > 0.35f);
        int tgt = um ? mi : ri;
        float bind = sigm(g_hbd[b] + 2.2f * ms);
        float conflict = clip01(1.0f - sS[tgt]);
        float owt = (0.15f + 0.85f * g_ws[b]) * (1.0f - 0.65f * sE[tgt] * conflict);
        float im = g_im[b];
        float km = um ? (0.22f + 0.38f * bind) : (0.78f + 0.18f * bind);
        float vm = um ? (0.45f + 0.35f * im) : (0.75f + 0.20f * im);

        out[O4_ + b] = mp;
        out[O5_ + b] = bind;
        out[O6_ + b] = owt * (1.0f / N_);
        out[O8_ + b] = ms;
        sh_tgt = tgt;
        sh_owt = owt;
        sh_bf = 0.5f + 0.5f * im;
        sh_ak = owt * km;
        sh_av = owt * vm;
    }
    __syncthreads();

    float ow = (n == sh_tgt) ? sh_owt : 0.0f;
    out[O9_ + idx] = ow;
    float up = clip01(wp * 0.98f + ow * sh_bf);
    out[O2_ + idx] = up;

    float s = up;
#pragma unroll
    for (int o = 16; o; o >>= 1) s += __shfl_xor_sync(0xffffffffu, s, o);
    __shared__ float ss4[4];
    if ((n & 31) == 0) ss4[n >> 5] = s;
    __syncthreads();
    if (n == 0) out[O7_ + b] = (ss4[0] + ss4[1] + ss4[2] + ss4[3]) * (1.0f / N_);

    // ---- fixup of the single target row in both big outputs ----
    const int t = sh_tgt;
    const float ak = sh_ak;
    const float av = sh_av;
    const size_t roff = ((size_t)b * N_ + t) * D_;

    float4 k = reinterpret_cast<const float4*>(wkeys + roff)[n];
    float4 c = reinterpret_cast<const float4*>(g_ck + (size_t)b * D_)[n];
    float4 ok;
    ok.x = k.x + ak * (c.x - k.x);
    ok.y = k.y + ak * (c.y - k.y);
    ok.z = k.z + ak * (c.z - k.z);
    ok.w = k.w + ak * (c.w - k.w);
    reinterpret_cast<float4*>(out + roff)[n] = ok;

    float4 v = reinterpret_cast<const float4*>(wvals + roff)[n];
    float4 cv = reinterpret_cast<const float4*>(g_cv + (size_t)b * D_)[n];
    float4 ov;
    ov.x = v.x + av * (cv.x - v.x);
    ov.y = v.y + av * (cv.y - v.y);
    ov.z = v.z + av * (cv.z - v.z);
    ov.w = v.w + av * (cv.w - v.w);
    reinterpret_cast<float4*>(out + O1_ + roff)[n] = ov;
}

// =====================================================================
extern "C" void kernel_launch(void* const* d_in, const int* in_sizes, int n_in,
                              void* d_out, int out_size)
{
    const float* hidden = (const float*)d_in[0];
    const float* wkeys  = (const float*)d_in[1];
    const float* wvals  = (const float*)d_in[2];
    const float* wprot  = (const float*)d_in[3];
    const float* wusage = (const float*)d_in[4];
    const float* wage   = (const float*)d_in[5];
    const float* Wk  = (const float*)d_in[6];
    const float* bk  = (const float*)d_in[7];
    const float* Wv  = (const float*)d_in[8];
    const float* bv  = (const float*)d_in[9];
    const float* Wwr = (const float*)d_in[10];
    const float* bwr = (const float*)d_in[11];
    const float* Wmg = (const float*)d_in[12];
    const float* bmg = (const float*)d_in[13];
    const float* Wbd = (const float*)d_in[14];
    const float* bbd = (const float*)d_in[15];
    const float* Wim = (const float*)d_in[16];
    const float* bim = (const float*)d_in[17];
    const float* Woc = (const float*)d_in[18];
    const float* boc = (const float*)d_in[19];
    const float* Wpr = (const float*)d_in[20];
    const float* bpr = (const float*)d_in[21];
    float* out = (float*)d_out;

    k_mega<<<NG_ + NH_ + NV_, 256>>>(hidden, wvals, Wk, bk, Wv, bv,
                                     Wwr, bwr, Wmg, bmg, Wbd, bbd, Wim, bim,
                                     Woc, boc, Wpr, bpr, out);
    k_score_keys<<<(B_ * N_) / 32, 256>>>(wkeys, out);
    k_selfix<<<B_, 128>>>(wprot, wusage, wage, wkeys, wvals, out);
}

// round 10
// speedup vs baseline: 1.1463x; 1.0190x over previous
#include <cuda_runtime.h>
#include <math.h>

#define B_ 1024
#define N_ 128
#define D_ 512

// ---- output layout (float32, concatenated in reference return order) ----
__device__ __host__ constexpr size_t KD_ = (size_t)B_ * N_ * D_;   // 67108864
__device__ __host__ constexpr size_t O1_ = KD_;                    // updated_values
__device__ __host__ constexpr size_t O2_ = 2 * KD_;                // updated_protection (B*N)
__device__ __host__ constexpr size_t O3_ = O2_ + (size_t)B_ * N_;  // write_strength (B)
__device__ __host__ constexpr size_t O4_ = O3_ + B_;               // merge_preference (B)
__device__ __host__ constexpr size_t O5_ = O4_ + B_;               // binding_strength (B)
__device__ __host__ constexpr size_t O6_ = O5_ + B_;               // overwrite.mean (B)
__device__ __host__ constexpr size_t O7_ = O6_ + B_;               // updated_protection.mean (B)
__device__ __host__ constexpr size_t O8_ = O7_ + B_;               // max_similarity (B)
__device__ __host__ constexpr size_t O9_ = O8_ + B_;               // overwrite (B*N)

// ---- scratch (__device__ globals; no allocations allowed) ----
__device__ float g_ck[B_ * D_];     // candidate_key (tanh)
__device__ float g_cv[B_ * D_];     // candidate_value (tanh)
__device__ float g_sim[B_ * N_];
__device__ float g_occ[B_ * N_];
__device__ float g_lprot[B_ * N_];
__device__ float g_ws[B_];
__device__ float g_im[B_];
__device__ float g_hmg[B_];
__device__ float g_hbd[B_];

__device__ __forceinline__ float sigm(float x) { return 1.0f / (1.0f + expf(-x)); }
__device__ __forceinline__ float clip01(float x) { return fminf(fmaxf(x, 0.0f), 1.0f); }
__device__ __forceinline__ float dot4(float4 a, float4 b) {
    return a.x * b.x + a.y * b.y + a.z * b.z + a.w * b.w;
}

// ---- packed fp32x2 helpers (sm_103a FFMA2 path; bit-exact IEEE fp32/lane) ----
#define PACK_F32X2(out, lo, hi) \
    asm("mov.b64 %0, {%1, %2};" : "=l"(out) : "f"(lo), "f"(hi))
#define UNPACK_F32X2(lo, hi, in) \
    asm("mov.b64 {%0, %1}, %2;" : "=f"(lo), "=f"(hi) : "l"(in))
#define FMA_F32X2(d, a, b, c) \
    asm("fma.rn.f32x2 %0, %1, %2, %3;" : "=l"(d) : "l"(a), "l"(b), "l"(c))

// =====================================================================
// Mega-kernel: block roles
//   [0, 256)        : GEMM (candidate key/value, tanh) — single-buffered,
//                     FFMA2 (f32x2) inner loop to halve fma-issue pressure
//   [256, 768)      : heads (4 scalar gemvs, 2 batches/block)
//   [768, 4864)     : score_vals streaming (8 warps x 4 rows)
// All roles are mutually independent.
// =====================================================================
#define NG_ 256
#define NH_ 512
#define NV_ 4096
#define MT_ 64
#define NT_ 64
#define KT_ 16

__global__ void __launch_bounds__(256, 4) k_mega(
    const float* __restrict__ hidden,
    const float* __restrict__ wvals,
    const float* __restrict__ Wk, const float* __restrict__ bk,
    const float* __restrict__ Wv, const float* __restrict__ bv,
    const float* __restrict__ Wwr, const float* __restrict__ bwr,
    const float* __restrict__ Wmg, const float* __restrict__ bmg,
    const float* __restrict__ Wbd, const float* __restrict__ bbd,
    const float* __restrict__ Wim, const float* __restrict__ bim,
    const float* __restrict__ Woc, const float* __restrict__ boc,
    const float* __restrict__ Wpr, const float* __restrict__ bpr,
    float* __restrict__ out)
{
    const int bid = blockIdx.x;
    const int tid = threadIdx.x;

    if (bid < NG_) {
        // ------------------- GEMM role (single-buffered, FFMA2) -------------------
        const int mx = bid & 15;
        const int ny = (bid >> 4) & 7;
        const int z = bid >> 7;
        const float* __restrict__ W    = z ? Wv : Wk;
        const float* __restrict__ bias = z ? bv : bk;
        float* outp = z ? g_cv : g_ck;

        const int tx = tid & 15;
        const int ty = tid >> 4;
        const int m0 = mx * MT_;
        const int n0 = ny * NT_;

        __shared__ __align__(16) float As[KT_][MT_];
        __shared__ __align__(16) float Bs[KT_][NT_];

        const int ar = tid >> 2;
        const int aq = tid & 3;
        const int br = tid >> 4;
        const int bc = tid & 15;

        const float* Aptr = hidden + (size_t)(m0 + ar) * D_ + aq * 4;
        const float* Bptr = W + (size_t)br * D_ + n0 + bc * 4;

        unsigned long long acc2[4][2];
#pragma unroll
        for (int i = 0; i < 4; i++) { acc2[i][0] = 0ULL; acc2[i][1] = 0ULL; }

        const int NCH = D_ / KT_;  // 32
#pragma unroll 1
        for (int kc = 0; kc < NCH; kc++) {
            float4 ra = *reinterpret_cast<const float4*>(Aptr + kc * KT_);
            float4 rb = *reinterpret_cast<const float4*>(Bptr + (size_t)kc * KT_ * D_);
            __syncthreads();   // previous chunk's compute done before overwrite
            As[aq * 4 + 0][ar] = ra.x;
            As[aq * 4 + 1][ar] = ra.y;
            As[aq * 4 + 2][ar] = ra.z;
            As[aq * 4 + 3][ar] = ra.w;
            *reinterpret_cast<float4*>(&Bs[br][bc * 4]) = rb;
            __syncthreads();
#pragma unroll
            for (int kk = 0; kk < KT_; kk++) {
                float4 a = *reinterpret_cast<const float4*>(&As[kk][ty * 4]);
                float4 b = *reinterpret_cast<const float4*>(&Bs[kk][tx * 4]);
                unsigned long long b01, b23;
                PACK_F32X2(b01, b.x, b.y);
                PACK_F32X2(b23, b.z, b.w);
                float av_[4] = {a.x, a.y, a.z, a.w};
#pragma unroll
                for (int i = 0; i < 4; i++) {
                    unsigned long long aa;
                    PACK_F32X2(aa, av_[i], av_[i]);
                    FMA_F32X2(acc2[i][0], aa, b01, acc2[i][0]);
                    FMA_F32X2(acc2[i][1], aa, b23, acc2[i][1]);
                }
            }
        }

        const float4 bv4 = *reinterpret_cast<const float4*>(bias + n0 + tx * 4);
#pragma unroll
        for (int i = 0; i < 4; i++) {
            float c0, c1, c2, c3;
            UNPACK_F32X2(c0, c1, acc2[i][0]);
            UNPACK_F32X2(c2, c3, acc2[i][1]);
            float4 o;
            o.x = tanhf(c0 + bv4.x);
            o.y = tanhf(c1 + bv4.y);
            o.z = tanhf(c2 + bv4.z);
            o.w = tanhf(c3 + bv4.w);
            *reinterpret_cast<float4*>(outp + (size_t)(m0 + ty * 4 + i) * D_ + n0 + tx * 4) = o;
        }
    } else if (bid < NG_ + NH_) {
        // ------------------- heads role (2 batches per block) -------------------
        const int g = tid >> 7;
        const int t = tid & 127;
        const int b = (bid - NG_) * 2 + g;

        float4 h = reinterpret_cast<const float4*>(hidden + (size_t)b * D_)[t];
        float4 w;
        w = reinterpret_cast<const float4*>(Wwr)[t];
        float pwr = dot4(h, w);
        w = reinterpret_cast<const float4*>(Wmg)[t];
        float pmg = dot4(h, w);
        w = reinterpret_cast<const float4*>(Wbd)[t];
        float pbd = dot4(h, w);
        w = reinterpret_cast<const float4*>(Wim)[t];
        float pim = dot4(h, w);

#pragma unroll
        for (int o = 16; o; o >>= 1) {
            pwr += __shfl_xor_sync(0xffffffffu, pwr, o);
            pmg += __shfl_xor_sync(0xffffffffu, pmg, o);
            pbd += __shfl_xor_sync(0xffffffffu, pbd, o);
            pim += __shfl_xor_sync(0xffffffffu, pim, o);
        }
        __shared__ float red[2][4][4];
        if ((t & 31) == 0) {
            int wi = t >> 5;
            red[g][wi][0] = pwr; red[g][wi][1] = pmg;
            red[g][wi][2] = pbd; red[g][wi][3] = pim;
        }
        __syncthreads();
        if (t == 0) {
            float dwr = red[g][0][0] + red[g][1][0] + red[g][2][0] + red[g][3][0];
            float dmg = red[g][0][1] + red[g][1][1] + red[g][2][1] + red[g][3][1];
            float dbd = red[g][0][2] + red[g][1][2] + red[g][2][2] + red[g][3][2];
            float dIm = red[g][0][3] + red[g][1][3] + red[g][2][3] + red[g][3][3];
            float ws = sigm(dwr + bwr[0]);
            g_ws[b] = ws;
            out[O3_ + b] = ws;
            g_im[b] = sigm(dIm + bim[0]);
            g_hmg[b] = dmg + bmg[0];
            g_hbd[b] = dbd + bbd[0];
        }
    } else {
        // ------------------- score_vals role -------------------
        const int w = (bid - NG_ - NH_) * 8 + (tid >> 5);
        const int lane = tid & 31;
        const int r0 = w * 4;

        const float4* wo = reinterpret_cast<const float4*>(Woc);
        const float4* wp = reinterpret_cast<const float4*>(Wpr);
        float4 o0 = wo[lane], o1 = wo[lane + 32], o2 = wo[lane + 64], o3 = wo[lane + 96];
        float4 q0 = wp[lane], q1 = wp[lane + 32], q2 = wp[lane + 64], q3 = wp[lane + 96];
        const float bocv = __ldg(boc);
        const float bprv = __ldg(bpr);

#pragma unroll
        for (int p = 0; p < 2; p++) {
            const int ra = r0 + 2 * p;
            const float4* va = reinterpret_cast<const float4*>(wvals + (size_t)ra * D_);
            const float4* vb = va + 128;
            float4 a0 = va[lane], a1 = va[lane + 32], a2 = va[lane + 64], a3 = va[lane + 96];
            float4 e0 = vb[lane], e1 = vb[lane + 32], e2 = vb[lane + 64], e3 = vb[lane + 96];

            float4* oa = reinterpret_cast<float4*>(out + O1_ + (size_t)ra * D_);
            float4* ob = oa + 128;
            oa[lane] = a0; oa[lane + 32] = a1; oa[lane + 64] = a2; oa[lane + 96] = a3;
            ob[lane] = e0; ob[lane + 32] = e1; ob[lane + 64] = e2; ob[lane + 96] = e3;

            float pa0 = dot4(a0, a0) + dot4(a1, a1) + dot4(a2, a2) + dot4(a3, a3);
            float pa1 = dot4(a0, o0) + dot4(a1, o1) + dot4(a2, o2) + dot4(a3, o3);
            float pa2 = dot4(a0, q0) + dot4(a1, q1) + dot4(a2, q2) + dot4(a3, q3);
            float pb0 = dot4(e0, e0) + dot4(e1, e1) + dot4(e2, e2) + dot4(e3, e3);
            float pb1 = dot4(e0, o0) + dot4(e1, o1) + dot4(e2, o2) + dot4(e3, o3);
            float pb2 = dot4(e0, q0) + dot4(e1, q1) + dot4(e2, q2) + dot4(e3, q3);
#pragma unroll
            for (int o = 16; o; o >>= 1) {
                pa0 += __shfl_xor_sync(0xffffffffu, pa0, o);
                pa1 += __shfl_xor_sync(0xffffffffu, pa1, o);
                pa2 += __shfl_xor_sync(0xffffffffu, pa2, o);
                pb0 += __shfl_xor_sync(0xffffffffu, pb0, o);
                pb1 += __shfl_xor_sync(0xffffffffu, pb1, o);
                pb2 += __shfl_xor_sync(0xffffffffu, pb2, o);
            }
            if (lane == 0) {
                float nocc = clip01(sqrtf(pa0) * 0.04419417382415922f);  // / sqrt(512)
                g_occ[ra] = clip01(0.5f * sigm(pa1 + bocv) + 0.5f * nocc);
                g_lprot[ra] = sigm(pa2 + bprv);
                nocc = clip01(sqrtf(pb0) * 0.04419417382415922f);
                g_occ[ra + 1] = clip01(0.5f * sigm(pb1 + bocv) + 0.5f * nocc);
                g_lprot[ra + 1] = sigm(pb2 + bprv);
            }
        }
    }
}

// =====================================================================
// Kernel 2: streaming pass over working_keys. One warp -> 4 rows.
// =====================================================================
__global__ void __launch_bounds__(256) k_score_keys(
    const float* __restrict__ wkeys, float* __restrict__ out)
{
    const int w = blockIdx.x * 8 + (threadIdx.x >> 5);
    const int lane = threadIdx.x & 31;
    const int r0 = w * 4;
    const int b = r0 >> 7;

    const float4* cr = reinterpret_cast<const float4*>(g_ck + (size_t)b * D_);
    float4 c0 = cr[lane], c1 = cr[lane + 32], c2 = cr[lane + 64], c3 = cr[lane + 96];

    float pss = dot4(c0, c0) + dot4(c1, c1) + dot4(c2, c2) + dot4(c3, c3);
#pragma unroll
    for (int o = 16; o; o >>= 1) pss += __shfl_xor_sync(0xffffffffu, pss, o);
    const float invnc = 1.0f / fmaxf(sqrtf(pss), 1e-6f);

#pragma unroll
    for (int p = 0; p < 2; p++) {
        const int ra = r0 + 2 * p;
        const float4* ka = reinterpret_cast<const float4*>(wkeys + (size_t)ra * D_);
        const float4* kb = ka + 128;
        float4 a0 = ka[lane], a1 = ka[lane + 32], a2 = ka[lane + 64], a3 = ka[lane + 96];
        float4 e0 = kb[lane], e1 = kb[lane + 32], e2 = kb[lane + 64], e3 = kb[lane + 96];

        float4* oa = reinterpret_cast<float4*>(out + (size_t)ra * D_);
        float4* ob = oa + 128;
        oa[lane] = a0; oa[lane + 32] = a1; oa[lane + 64] = a2; oa[lane + 96] = a3;
        ob[lane] = e0; ob[lane + 32] = e1; ob[lane + 64] = e2; ob[lane + 96] = e3;

        float pa0 = dot4(a0, c0) + dot4(a1, c1) + dot4(a2, c2) + dot4(a3, c3);
        float pa1 = dot4(a0, a0) + dot4(a1, a1) + dot4(a2, a2) + dot4(a3, a3);
        float pb0 = dot4(e0, c0) + dot4(e1, c1) + dot4(e2, c2) + dot4(e3, c3);
        float pb1 = dot4(e0, e0) + dot4(e1, e1) + dot4(e2, e2) + dot4(e3, e3);
#pragma unroll
        for (int o = 16; o; o >>= 1) {
            pa0 += __shfl_xor_sync(0xffffffffu, pa0, o);
            pa1 += __shfl_xor_sync(0xffffffffu, pa1, o);
            pb0 += __shfl_xor_sync(0xffffffffu, pb0, o);
            pb1 += __shfl_xor_sync(0xffffffffu, pb1, o);
        }
        if (lane == 0) {
            g_sim[ra]     = pa0 * invnc / fmaxf(sqrtf(pa1), 1e-6f);
            g_sim[ra + 1] = pb0 * invnc / fmaxf(sqrtf(pb1), 1e-6f);
        }
    }
}

// =====================================================================
// Kernel 3: per-batch selection + small outputs + target-row fixup.
// =====================================================================
__global__ void __launch_bounds__(128) k_selfix(
    const float* __restrict__ wprot, const float* __restrict__ wusage,
    const float* __restrict__ wage,
    const float* __restrict__ wkeys, const float* __restrict__ wvals,
    float* __restrict__ out)
{
    const int b = blockIdx.x;
    const int n = threadIdx.x;
    const int idx = b * N_ + n;

    float sim = g_sim[idx];
    float occ = g_occ[idx];
    float lp  = g_lprot[idx];
    float wp  = wprot[idx];
    float ep = clip01(0.4f * lp + 0.6f * wp);
    float eu = clip01(0.5f * occ + 0.5f * wusage[idx]);
    float ea = clip01(wage[idx]);
    float rs = 1.15f * (1.0f - occ) + 0.85f * (1.0f - ep) + 0.65f * ea
             + 0.45f * (1.0f - eu) + 0.25f * (1.0f - sim);

    __shared__ float sS[N_], sO[N_], sU[N_], sA[N_], sE[N_];
    sS[n] = sim; sO[n] = occ; sU[n] = eu; sA[n] = ea; sE[n] = ep;

    float v1 = sim; int i1 = n;
    float v2 = rs;  int i2 = n;
#pragma unroll
    for (int o = 16; o; o >>= 1) {
        float ov = __shfl_down_sync(0xffffffffu, v1, o);
        int   oi = __shfl_down_sync(0xffffffffu, i1, o);
        if (ov > v1 || (ov == v1 && oi < i1)) { v1 = ov; i1 = oi; }
        ov = __shfl_down_sync(0xffffffffu, v2, o);
        oi = __shfl_down_sync(0xffffffffu, i2, o);
        if (ov > v2 || (ov == v2 && oi < i2)) { v2 = ov; i2 = oi; }
    }
    __shared__ float wv1[4], wv2[4];
    __shared__ int wi1[4], wi2[4];
    if ((n & 31) == 0) {
        int w = n >> 5;
        wv1[w] = v1; wi1[w] = i1; wv2[w] = v2; wi2[w] = i2;
    }
    __syncthreads();

    __shared__ int sh_tgt;
    __shared__ float sh_owt, sh_bf, sh_ak, sh_av;
    if (n == 0) {
        float bv = wv1[0]; int bi = wi1[0];
#pragma unroll
        for (int w = 1; w < 4; w++)
            if (wv1[w] > bv || (wv1[w] == bv && wi1[w] < bi)) { bv = wv1[w]; bi = wi1[w]; }
        int mi = bi;
        float rbv = wv2[0]; int ri = wi2[0];
#pragma unroll
        for (int w = 1; w < 4; w++)
            if (wv2[w] > rbv || (wv2[w] == rbv && wi2[w] < ri)) { rbv = wv2[w]; ri = wi2[w]; }

        float ms = sS[mi], mo = sO[mi], mu = sU[mi], ma = sA[mi];
        float mp = sigm(g_hmg[b] + 2.4f * ms + 1.6f * (mo - 0.5f)
                        + 1.0f * (mu - 0.5f) - 0.8f * ma);
        bool um = (mp >= 0.5f) && (ms > 0.55f) && (mo > 0.35f);
        int tgt = um ? mi : ri;
        float bind = sigm(g_hbd[b] + 2.2f * ms);
        float conflict = clip01(1.0f - sS[tgt]);
        float owt = (0.15f + 0.85f * g_ws[b]) * (1.0f - 0.65f * sE[tgt] * conflict);
        float im = g_im[b];
        float km = um ? (0.22f + 0.38f * bind) : (0.78f + 0.18f * bind);
        float vm = um ? (0.45f + 0.35f * im) : (0.75f + 0.20f * im);

        out[O4_ + b] = mp;
        out[O5_ + b] = bind;
        out[O6_ + b] = owt * (1.0f / N_);
        out[O8_ + b] = ms;
        sh_tgt = tgt;
        sh_owt = owt;
        sh_bf = 0.5f + 0.5f * im;
        sh_ak = owt * km;
        sh_av = owt * vm;
    }
    __syncthreads();

    float ow = (n == sh_tgt) ? sh_owt : 0.0f;
    out[O9_ + idx] = ow;
    float up = clip01(wp * 0.98f + ow * sh_bf);
    out[O2_ + idx] = up;

    float s = up;
#pragma unroll
    for (int o = 16; o; o >>= 1) s += __shfl_xor_sync(0xffffffffu, s, o);
    __shared__ float ss4[4];
    if ((n & 31) == 0) ss4[n >> 5] = s;
    __syncthreads();
    if (n == 0) out[O7_ + b] = (ss4[0] + ss4[1] + ss4[2] + ss4[3]) * (1.0f / N_);

    // ---- fixup of the single target row in both big outputs ----
    const int t = sh_tgt;
    const float ak = sh_ak;
    const float av = sh_av;
    const size_t roff = ((size_t)b * N_ + t) * D_;

    float4 k = reinterpret_cast<const float4*>(wkeys + roff)[n];
    float4 c = reinterpret_cast<const float4*>(g_ck + (size_t)b * D_)[n];
    float4 ok;
    ok.x = k.x + ak * (c.x - k.x);
    ok.y = k.y + ak * (c.y - k.y);
    ok.z = k.z + ak * (c.z - k.z);
    ok.w = k.w + ak * (c.w - k.w);
    reinterpret_cast<float4*>(out + roff)[n] = ok;

    float4 v = reinterpret_cast<const float4*>(wvals + roff)[n];
    float4 cv = reinterpret_cast<const float4*>(g_cv + (size_t)b * D_)[n];
    float4 ov;
    ov.x = v.x + av * (cv.x - v.x);
    ov.y = v.y + av * (cv.y - v.y);
    ov.z = v.z + av * (cv.z - v.z);
    ov.w = v.w + av * (cv.w - v.w);
    reinterpret_cast<float4*>(out + O1_ + roff)[n] = ov;
}

// =====================================================================
extern "C" void kernel_launch(void* const* d_in, const int* in_sizes, int n_in,
                              void* d_out, int out_size)
{
    const float* hidden = (const float*)d_in[0];
    const float* wkeys  = (const float*)d_in[1];
    const float* wvals  = (const float*)d_in[2];
    const float* wprot  = (const float*)d_in[3];
    const float* wusage = (const float*)d_in[4];
    const float* wage   = (const float*)d_in[5];
    const float* Wk  = (const float*)d_in[6];
    const float* bk  = (const float*)d_in[7];
    const float* Wv  = (const float*)d_in[8];
    const float* bv  = (const float*)d_in[9];
    const float* Wwr = (const float*)d_in[10];
    const float* bwr = (const float*)d_in[11];
    const float* Wmg = (const float*)d_in[12];
    const float* bmg = (const float*)d_in[13];
    const float* Wbd = (const float*)d_in[14];
    const float* bbd = (const float*)d_in[15];
    const float* Wim = (const float*)d_in[16];
    const float* bim = (const float*)d_in[17];
    const float* Woc = (const float*)d_in[18];
    const float* boc = (const float*)d_in[19];
    const float* Wpr = (const float*)d_in[20];
    const float* bpr = (const float*)d_in[21];
    float* out = (float*)d_out;

    k_mega<<<NG_ + NH_ + NV_, 256>>>(hidden, wvals, Wk, bk, Wv, bv,
                                     Wwr, bwr, Wmg, bmg, Wbd, bbd, Wim, bim,
                                     Woc, boc, Wpr, bpr, out);
    k_score_keys<<<(B_ * N_) / 32, 256>>>(wkeys, out);
    k_selfix<<<B_, 128>>>(wprot, wusage, wage, wkeys, wvals, out);
}